// round 3
// baseline (speedup 1.0000x reference)
#include <cuda_runtime.h>
#include <cuda_bf16.h>
#include <stdint.h>

// ---------------------------------------------------------------------------
// Hodge1LapEdgeEncoder
//
// Output buffer (float32, concatenated):
//   [0, P)        : out_idx rows  (P = B*n*n), value = b*n + i
//   [P, 2P)       : out_idx cols,              value = b*n + j
//   [2P, 2P+P*D)  : out_val, dense[B,n,n,D] = padding + scatter_add(edge vals)
//
// edge val[e,:] = edge_attr[e,:] + pestat[e,0] * fc_w[:,0]
// target slot   = (g, u%n, v%n), g = u/n, u = edge_index[0,e], v = edge_index[1,e]
// ---------------------------------------------------------------------------

// Kernel 1 (fused): idx pattern + padding broadcast init, D % 4 == 0 path.
// Work item space: [0, P) -> idx rows+cols; [P, P + totalV/4) -> float4 init.
__global__ void k_init_fused_v4(float* __restrict__ out,     // full out buffer
                                const float4* __restrict__ pad4,
                                long long P, int n, int D4)
{
    long long totalI = P;                       // idx items (each writes 2 floats)
    long long totalV4 = P * (long long)D4;      // float4 items in value region
    long long tot = totalI + totalV4;
    float4* val4 = (float4*)(out + 2 * P);

    long long stride = (long long)gridDim.x * blockDim.x;
    for (long long t = (long long)blockIdx.x * blockDim.x + threadIdx.x;
         t < tot; t += stride) {
        if (t < totalI) {
            long long nn  = (long long)n * n;
            int b   = (int)(t / nn);
            int rem = (int)(t - (long long)b * nn);
            int i   = rem / n;
            int j   = rem - i * n;
            int base = b * n;
            out[t]     = (float)(base + i);
            out[P + t] = (float)(base + j);
        } else {
            long long v = t - totalI;
            val4[v] = __ldg(&pad4[(int)(v % D4)]);
        }
    }
}

// Kernel 1 (scalar fallback when D % 4 != 0).
__global__ void k_init_fused_s(float* __restrict__ out,
                               const float* __restrict__ pad,
                               long long P, int n, int D)
{
    long long totalI = P;
    long long totalV = P * (long long)D;
    long long tot = totalI + totalV;
    float* val = out + 2 * P;

    long long stride = (long long)gridDim.x * blockDim.x;
    for (long long t = (long long)blockIdx.x * blockDim.x + threadIdx.x;
         t < tot; t += stride) {
        if (t < totalI) {
            long long nn  = (long long)n * n;
            int b   = (int)(t / nn);
            int rem = (int)(t - (long long)b * nn);
            int i   = rem / n;
            int j   = rem - i * n;
            int base = b * n;
            out[t]     = (float)(base + i);
            out[P + t] = (float)(base + j);
        } else {
            long long v = t - totalI;
            val[v] = __ldg(&pad[(int)(v % D)]);
        }
    }
}

// Kernel 2 (vector): scatter-add edge contributions. One thread per
// (edge, 4-float chunk). Consecutive threads share an edge -> coalesced
// edge_attr loads and contiguous atomic targets.
__global__ void k_scatter_v4(const int*    __restrict__ ei,      // [2, E]
                             const float*  __restrict__ pestat,  // [E, K]
                             const float4* __restrict__ ea4,     // [E, D/4]
                             const float4* __restrict__ w4,      // [D/4]
                             float*        __restrict__ val,     // dense [B,n,n,D]
                             int E, int K, int D4, int n)
{
    long long tot = (long long)E * D4;
    long long stride = (long long)gridDim.x * blockDim.x;
    for (long long t = (long long)blockIdx.x * blockDim.x + threadIdx.x;
         t < tot; t += stride) {
        int e = (int)(t / D4);
        int c = (int)(t - (long long)e * D4);

        int u = __ldg(&ei[e]);
        int v = __ldg(&ei[E + e]);
        int g  = u / n;
        int ru = u - g * n;
        int rv = v % n;

        float  p = __ldg(&pestat[(long long)e * K]);
        float4 a = ea4[(long long)e * D4 + c];
        float4 w = __ldg(&w4[c]);

        long long base = (((long long)g * n + ru) * n + rv) * ((long long)D4 * 4)
                         + (long long)c * 4;
        atomicAdd(val + base + 0, a.x + p * w.x);
        atomicAdd(val + base + 1, a.y + p * w.y);
        atomicAdd(val + base + 2, a.z + p * w.z);
        atomicAdd(val + base + 3, a.w + p * w.w);
    }
}

// Kernel 2 (scalar fallback): one thread per (edge, d).
__global__ void k_scatter_s(const int*   __restrict__ ei,
                            const float* __restrict__ pestat,
                            const float* __restrict__ ea,
                            const float* __restrict__ w,
                            float*       __restrict__ val,
                            int E, int K, int D, int n)
{
    long long tot = (long long)E * D;
    long long stride = (long long)gridDim.x * blockDim.x;
    for (long long t = (long long)blockIdx.x * blockDim.x + threadIdx.x;
         t < tot; t += stride) {
        int e = (int)(t / D);
        int d = (int)(t - (long long)e * D);

        int u = __ldg(&ei[e]);
        int v = __ldg(&ei[E + e]);
        int g  = u / n;
        int ru = u - g * n;
        int rv = v % n;

        float p = __ldg(&pestat[(long long)e * K]);
        float a = ea[(long long)e * D + d];
        float x = a + p * __ldg(&w[d]);

        long long base = (((long long)g * n + ru) * n + rv) * (long long)D + d;
        atomicAdd(val + base, x);
    }
}

static inline int grid_for(long long work, int tb)
{
    long long g = (work + tb - 1) / tb;
    if (g > 1048576) g = 1048576;   // grid-stride handles the rest
    if (g < 1) g = 1;
    return (int)g;
}

extern "C" void kernel_launch(void* const* d_in, const int* in_sizes, int n_in,
                              void* d_out, int out_size)
{
    // metadata order: edge_index, pestat, edge_attr, batch, fc_w, padding, (scalars)
    const int*   ei     = (const int*)  d_in[0];
    const float* pestat = (const float*)d_in[1];
    const float* ea     = (const float*)d_in[2];
    const float* fc_w   = (const float*)d_in[4];
    const float* pad    = (const float*)d_in[5];

    // Shape derivation (host-side, from element counts only).
    const int E = in_sizes[0] / 2;
    const int K = in_sizes[1] / E;
    const int D = in_sizes[2] / E;
    const int N = in_sizes[3];                            // total nodes = B * n
    const long long P = (long long)out_size / (D + 2);    // B * n * n
    const int n = (int)(P / N);                           // nodes per graph

    float* out = (float*)d_out;
    float* val = out + 2 * P;                             // dense value region

    const int TB = 256;

    // 1) fused idx pattern + padding init
    if ((D % 4) == 0) {
        int D4 = D / 4;
        long long tot = P + P * (long long)D4;
        k_init_fused_v4<<<grid_for(tot, TB), TB>>>(out, (const float4*)pad,
                                                   P, n, D4);
    } else {
        long long tot = P + P * (long long)D;
        k_init_fused_s<<<grid_for(tot, TB), TB>>>(out, pad, P, n, D);
    }

    // 2) edge scatter-add
    if ((D % 4) == 0) {
        int D4 = D / 4;
        long long tot = (long long)E * D4;
        k_scatter_v4<<<grid_for(tot, TB), TB>>>(ei, pestat, (const float4*)ea,
                                                (const float4*)fc_w, val,
                                                E, K, D4, n);
    } else {
        long long tot = (long long)E * D;
        k_scatter_s<<<grid_for(tot, TB), TB>>>(ei, pestat, ea, fc_w, val,
                                               E, K, D, n);
    }
}

// round 4
// speedup vs baseline: 2.0031x; 2.0031x over previous
#include <cuda_runtime.h>
#include <cuda_bf16.h>
#include <stdint.h>

// ---------------------------------------------------------------------------
// Hodge1LapEdgeEncoder
//
// Output buffer (float32, concatenated):
//   [0, P)        : out_idx rows  (P = B*n*n), value = b*n + i
//   [P, 2P)       : out_idx cols,              value = b*n + j
//   [2P, 2P+P*D)  : out_val, dense[B,n,n,D] = padding + scatter_add(edge vals)
//
// edge val[e,:] = edge_attr[e,:] + pestat[e,0] * fc_w[:,0]
// target slot   = (g, u%n, v%n), g = u/n, u = edge_index[0,e], v = edge_index[1,e]
// ---------------------------------------------------------------------------

__device__ __forceinline__ void red_add_v4(float* dst, float4 r)
{
#if __CUDA_ARCH__ >= 900
    asm volatile("red.global.add.v4.f32 [%0], {%1, %2, %3, %4};"
                 :: "l"(dst), "f"(r.x), "f"(r.y), "f"(r.z), "f"(r.w)
                 : "memory");
#else
    atomicAdd(dst + 0, r.x);
    atomicAdd(dst + 1, r.y);
    atomicAdd(dst + 2, r.z);
    atomicAdd(dst + 3, r.w);
#endif
}

// ===========================================================================
// Fast path: n and D4 powers of two, D % 4 == 0, n % 4 == 0, D4 <= 256.
// ===========================================================================

// Init (fused, block-partitioned): blocks [0, idxBlocks) write the idx
// pattern (float4-vectorized); the rest broadcast the padding row.
// One item per thread, no loops, no divisions.
__global__ void k_init_p2(float* __restrict__ out,
                          const float4* __restrict__ pad4,
                          int sn,            // log2(n)
                          long long P,       // B*n*n
                          int D4,            // D/4
                          int idxBlocks)
{
    if ((int)blockIdx.x < idxBlocks) {
        // idx region, vectorized: item covers 4 consecutive (b,i,j..j+3).
        long long P4 = P >> 2;
        long long t = (long long)blockIdx.x * blockDim.x + threadIdx.x;
        if (t >= P4) return;
        long long q   = t << 2;                 // first flat element
        int nm1  = (1 << sn) - 1;
        long long nnm1 = ((long long)1 << (2 * sn)) - 1;
        int b    = (int)(q >> (2 * sn));
        int rem  = (int)(q & nnm1);
        int i    = rem >> sn;
        int j    = rem & nm1;                   // j..j+3 stay in-row (n%4==0)
        float rv = (float)((b << sn) + i);
        float cv = (float)((b << sn) + j);
        float4* rows4 = (float4*)out;
        float4* cols4 = (float4*)(out + P);
        rows4[t] = make_float4(rv, rv, rv, rv);
        cols4[t] = make_float4(cv, cv + 1.0f, cv + 2.0f, cv + 3.0f);
    } else {
        // value region: one float4 store per thread.
        long long v = (long long)((int)blockIdx.x - idxBlocks) * blockDim.x
                      + threadIdx.x;
        long long V4 = P * (long long)D4;
        if (v >= V4) return;
        // 256 % D4 == 0 (D4 is pow2 <= 256) => column id from threadIdx only.
        int c = (int)threadIdx.x & (D4 - 1);
        float4* val4 = (float4*)(out + 2 * P);
        val4[v] = __ldg(&pad4[c]);
    }
}

// Scatter (pow2): one thread per (edge, float4 chunk); one red.v4 per thread.
__global__ void k_scatter_p2(const int*    __restrict__ ei,      // [2, E]
                             const float*  __restrict__ pestat,  // [E, K]
                             const float4* __restrict__ ea4,     // [E, D/4]
                             const float4* __restrict__ w4,      // [D/4]
                             float*        __restrict__ val,     // [B,n,n,D]
                             int E, int K, int s4, int sn)
{
    int tot = E << s4;                          // E * D4 (fits in int)
    int t = blockIdx.x * blockDim.x + threadIdx.x;
    if (t >= tot) return;
    int e = t >> s4;
    int c = t & ((1 << s4) - 1);
    int nm1 = (1 << sn) - 1;

    int u = __ldg(&ei[e]);
    int v = __ldg(&ei[E + e]);
    int g  = u >> sn;
    int ru = u & nm1;
    int rv = v & nm1;

    float  p = __ldg(&pestat[(long long)e * K]);
    float4 a = __ldg(&ea4[((long long)e << s4) + c]);
    float4 w = __ldg(&w4[c]);

    float4 r;
    r.x = a.x + p * w.x;
    r.y = a.y + p * w.y;
    r.z = a.z + p * w.z;
    r.w = a.w + p * w.w;

    long long slot = ((long long)g << (2 * sn)) | ((long long)ru << sn) | rv;
    float* dst = val + (slot << (s4 + 2)) + (c << 2);   // slot*D + c*4
    red_add_v4(dst, r);
}

// ===========================================================================
// Generic fallbacks (any n, any D).
// ===========================================================================

__global__ void k_init_fused_s(float* __restrict__ out,
                               const float* __restrict__ pad,
                               long long P, int n, int D)
{
    long long totalI = P;
    long long totalV = P * (long long)D;
    long long tot = totalI + totalV;
    float* val = out + 2 * P;

    long long stride = (long long)gridDim.x * blockDim.x;
    for (long long t = (long long)blockIdx.x * blockDim.x + threadIdx.x;
         t < tot; t += stride) {
        if (t < totalI) {
            long long nn  = (long long)n * n;
            int b   = (int)(t / nn);
            int rem = (int)(t - (long long)b * nn);
            int i   = rem / n;
            int j   = rem - i * n;
            int base = b * n;
            out[t]     = (float)(base + i);
            out[P + t] = (float)(base + j);
        } else {
            long long v = t - totalI;
            val[v] = __ldg(&pad[(int)(v % D)]);
        }
    }
}

__global__ void k_scatter_s(const int*   __restrict__ ei,
                            const float* __restrict__ pestat,
                            const float* __restrict__ ea,
                            const float* __restrict__ w,
                            float*       __restrict__ val,
                            int E, int K, int D, int n)
{
    long long tot = (long long)E * D;
    long long stride = (long long)gridDim.x * blockDim.x;
    for (long long t = (long long)blockIdx.x * blockDim.x + threadIdx.x;
         t < tot; t += stride) {
        int e = (int)(t / D);
        int d = (int)(t - (long long)e * D);

        int u = __ldg(&ei[e]);
        int v = __ldg(&ei[E + e]);
        int g  = u / n;
        int ru = u - g * n;
        int rv = v % n;

        float p = __ldg(&pestat[(long long)e * K]);
        float a = ea[(long long)e * D + d];
        float x = a + p * __ldg(&w[d]);

        long long base = (((long long)g * n + ru) * n + rv) * (long long)D + d;
        atomicAdd(val + base, x);
    }
}

// ===========================================================================

static inline bool is_pow2(int x) { return x > 0 && (x & (x - 1)) == 0; }
static inline int  ilog2(int x)   { int s = 0; while ((1 << s) < x) s++; return s; }

static inline int grid_for(long long work, int tb)
{
    long long g = (work + tb - 1) / tb;
    if (g > 1048576) g = 1048576;
    if (g < 1) g = 1;
    return (int)g;
}

extern "C" void kernel_launch(void* const* d_in, const int* in_sizes, int n_in,
                              void* d_out, int out_size)
{
    // metadata order: edge_index, pestat, edge_attr, batch, fc_w, padding
    const int*   ei     = (const int*)  d_in[0];
    const float* pestat = (const float*)d_in[1];
    const float* ea     = (const float*)d_in[2];
    const float* fc_w   = (const float*)d_in[4];
    const float* pad    = (const float*)d_in[5];

    const int E = in_sizes[0] / 2;
    const int K = in_sizes[1] / E;
    const int D = in_sizes[2] / E;
    const int N = in_sizes[3];                            // total nodes = B*n
    const long long P = (long long)out_size / (D + 2);    // B*n*n
    const int n = (int)(P / N);                           // nodes per graph

    float* out = (float*)d_out;
    float* val = out + 2 * P;

    const int TB = 256;
    const int D4 = D / 4;

    const bool fast = (D % 4 == 0) && (n % 4 == 0) &&
                      is_pow2(n) && is_pow2(D4) && D4 <= 256 &&
                      ((long long)E * D4 < (1LL << 31));

    if (fast) {
        const int sn = ilog2(n);
        const int s4 = ilog2(D4);

        // fused init: idx blocks + value blocks, one item per thread
        long long P4 = P >> 2;
        long long V4 = P * (long long)D4;
        int idxBlocks = (int)((P4 + TB - 1) / TB);
        int valBlocks = (int)((V4 + TB - 1) / TB);
        k_init_p2<<<idxBlocks + valBlocks, TB>>>(out, (const float4*)pad,
                                                 sn, P, D4, idxBlocks);

        // scatter with vector reductions
        int tot = E << s4;
        k_scatter_p2<<<(tot + TB - 1) / TB, TB>>>(ei, pestat,
                                                  (const float4*)ea,
                                                  (const float4*)fc_w,
                                                  val, E, K, s4, sn);
    } else {
        long long tot = P + P * (long long)D;
        k_init_fused_s<<<grid_for(tot, TB), TB>>>(out, pad, P, n, D);

        long long st = (long long)E * D;
        k_scatter_s<<<grid_for(st, TB), TB>>>(ei, pestat, ea, fc_w, val,
                                              E, K, D, n);
    }
}